// round 8
// baseline (speedup 1.0000x reference)
#include <cuda_runtime.h>
#include <math_constants.h>

// Exact kNN graph via uniform grid + warp-converged ring search.
// PyG knn_graph(loop=False): B=16 graphs x n=4096 pts, D=3, k=16.
// Output (float32 flat): [nbr_global | centers | topk_d2], each total_n*K,
// ordering (b*n+i)*K + m (matches reference reshape(-1)).

#define K     16
#define KP1   17
#define NPER  4096
#define TPB   256
#define CPG   (NPER / TPB)   // 16 CTAs per graph
#define NG    16
#define G     20
#define GC    (G * G * G)    // 8000
#define GCP   8192
#define LO    (-4.5f)
#define HCELL 0.45f

#define PB       10                 // pending u64 slots per thread
#define SLOT_B   (TPB * 8u)         // 2048 bytes between a thread's slots
#define FLUSH_B  (6u * SLOT_B)      // flush when cnt >= 6

// smem byte offsets (query kernel)
#define SM_PTS    0                         // float4[4096]          65536
#define SM_PEND   65536                     // u64[PB][256]          20480
#define SM_SIDX   (65536 + 20480)           // u16[4096]              8192
#define SM_START  (65536 + 20480 + 8192)    // u16[GC+1]             16002
#define SM_TOTAL  110720

__device__ float4         g_pts  [NG][NPER];   // (x, y, z, |p|^2) cell-sorted
__device__ unsigned short g_sidx [NG][NPER];   // sorted slot -> original idx
__device__ unsigned short g_start[NG][GC + 1]; // cumulative cell starts

__device__ __forceinline__ int cellCoord(float v) {
    int c = (int)floorf((v - LO) * (1.0f / HCELL));
    return min(G - 1, max(0, c));
}

#define UNPACK2(lo, hi, in) \
    asm("mov.b64 {%0, %1}, %2;" : "=r"(lo), "=r"(hi) : "l"(in))

// ---------------------------------------------------------------- build ----
__global__ __launch_bounds__(TPB, 1)
void knn_build_kernel(const float* __restrict__ pos)
{
    __shared__ int cnt[GCP];
    __shared__ int partial[TPB];
    const int g = blockIdx.x, tid = threadIdx.x, base = g * NPER;
    const float* gp = pos + (size_t)base * 3;

    for (int i = tid; i < GCP; i += TPB) cnt[i] = 0;
    __syncthreads();

    for (int p = tid; p < NPER; p += TPB) {
        const float x = gp[3 * p], y = gp[3 * p + 1], z = gp[3 * p + 2];
        atomicAdd(&cnt[(cellCoord(z) * G + cellCoord(y)) * G + cellCoord(x)], 1);
    }
    __syncthreads();

    // exclusive scan over GCP (32 cells/thread)
    const int c0 = tid * 32;
    int s = 0;
    for (int i = 0; i < 32; ++i) s += cnt[c0 + i];
    partial[tid] = s;
    __syncthreads();
    if (tid == 0) {
        int run = 0;
        for (int t = 0; t < TPB; ++t) { const int v = partial[t]; partial[t] = run; run += v; }
    }
    __syncthreads();
    int run = partial[tid];
    for (int i = 0; i < 32; ++i) { const int v = cnt[c0 + i]; cnt[c0 + i] = run; run += v; }
    __syncthreads();

    // publish cumulative starts BEFORE the scatter mutates the cursors
    for (int i = tid; i <= GC; i += TPB)
        g_start[g][i] = (unsigned short)cnt[i];
    __syncthreads();

    // scatter: (x,y,z,|p|^2); norm op order matches the dot chain so the
    // self-distance evaluates to exactly +0 in the query kernel.
    for (int p = tid; p < NPER; p += TPB) {
        const float x = gp[3 * p], y = gp[3 * p + 1], z = gp[3 * p + 2];
        const int id = (cellCoord(z) * G + cellCoord(y)) * G + cellCoord(x);
        const int slot = atomicAdd(&cnt[id], 1);
        g_pts [g][slot] = make_float4(x, y, z, fmaf(z, z, fmaf(y, y, x * x)));
        g_sidx[g][slot] = (unsigned short)p;
    }
}

// ---------------------------------------------------------------- query ----

// One candidate: LDS.128 broadcast, distance (reference op order), branchless
// predicated FIFO push gated by (own-range membership) && (d <= worst).
#define CAND(jv)                                                              \
    do {                                                                      \
        const float4 P_ = pts[jv];                                            \
        const float dot_ = fmaf(qz, P_.z, fmaf(qy, P_.y, qx * P_.x));         \
        const float d_   = fmaf(-2.f, dot_, qs + P_.w);                       \
        const unsigned inr_ = ((unsigned)((jv) - llo) < lspan) ? 1u : 0u;     \
        unsigned long long kk_;                                               \
        asm("mov.b64 %0, {%1, %2};" : "=l"(kk_)                               \
            : "r"((unsigned)(jv)), "r"(__float_as_uint(d_)));                 \
        unsigned inc_;                                                        \
        asm volatile(                                                         \
            "{\n\t.reg .pred p;\n\t"                                          \
            "setp.ne.u32 p, %1, 0;\n\t"                                       \
            "setp.le.and.f32 p, %2, %3, p;\n\t"                               \
            "selp.u32 %0, %4, 0, p;\n\t"                                      \
            "@p st.shared.b64 [%5], %6;\n\t}"                                 \
            : "=r"(inc_)                                                      \
            : "r"(inr_), "f"(d_), "f"(worstf), "n"(SLOT_B),                   \
              "r"(pbase + offb), "l"(kk_)                                     \
            : "memory");                                                      \
        offb += inc_;                                                         \
    } while (0)

// Drain this lane's FIFO into the sorted K+1 list (per-lane divergent guard,
// the R3/R6-validated pattern). Keys hold the SORTED slot; map to the original
// index here (drains are rare).
#define DRAIN()                                                               \
    {                                                                         \
        const int cnt_ = (int)(offb >> 11);                                   \
        offb = 0;                                                             \
        const unsigned long long* myp_ = pend + tid;                          \
        _Pragma("unroll 1")                                                   \
        for (int p_ = 0; p_ < cnt_; ++p_) {                                   \
            const unsigned long long kk_ = myp_[(size_t)p_ * TPB];            \
            unsigned lo_, hi_;                                                \
            UNPACK2(lo_, hi_, kk_);                                           \
            float dc_ = __uint_as_float(hi_);                                 \
            int   ic_ = (int)sidx[lo_];                                       \
            if (dc_ < worstf) {                                               \
                _Pragma("unroll")                                             \
                for (int m_ = 0; m_ < KP1; ++m_) {                            \
                    const bool  sw_ = dc_ < bd[m_];                           \
                    const float fo_ = sw_ ? bd[m_] : dc_;                     \
                    const int   io_ = sw_ ? bi[m_] : ic_;                     \
                    bd[m_] = sw_ ? dc_ : bd[m_];                              \
                    bi[m_] = sw_ ? ic_ : bi[m_];                              \
                    dc_ = fo_; ic_ = io_;                                     \
                }                                                             \
                worstf = bd[KP1 - 1];                                         \
            }                                                                 \
        }                                                                     \
    }

// Warp-union lockstep scan of one x-contiguous row segment. Lanes with an
// invalid row / done status contribute an empty range; out-of-own-range
// candidates are rejected by the inr_ predicate (no duplicates, exact
// coverage). Uniform j => LDS broadcast + legal uniform flush votes.
#define SCAN_SEG(valid_, rb_, x0_, x1_)                                       \
    {                                                                         \
        unsigned llo = 0, lspan = 0;                                          \
        unsigned ulo_in = 0xFFFFFFFFu, uhi_in = 0;                            \
        if ((valid_) && !done) {                                              \
            llo = sstart[(rb_) + (x0_)];                                      \
            const unsigned lhi_ = sstart[(rb_) + (x1_) + 1];                  \
            lspan = lhi_ - llo;                                               \
            ulo_in = llo; uhi_in = lhi_;                                      \
        }                                                                     \
        const unsigned ulo = __reduce_min_sync(0xFFFFFFFFu, ulo_in);          \
        const unsigned uhi = __reduce_max_sync(0xFFFFFFFFu, uhi_in);          \
        unsigned j = ulo;                                                     \
        for (; j + 1 < uhi; j += 2) {                                         \
            CAND(j);                                                          \
            CAND(j + 1);                                                      \
            if ((j & 2u) == 2u &&                                             \
                __any_sync(0xFFFFFFFFu, offb >= FLUSH_B)) DRAIN();            \
        }                                                                     \
        if (j < uhi) CAND(j);                                                 \
        if (__any_sync(0xFFFFFFFFu, offb >= FLUSH_B)) DRAIN();                \
    }

__global__ __launch_bounds__(TPB, 2)
void knn_query_kernel(float* __restrict__ out, int total_n)
{
    extern __shared__ char smem_raw[];
    float4*             pts    = (float4*)(smem_raw + SM_PTS);
    unsigned long long* pend   = (unsigned long long*)(smem_raw + SM_PEND);
    unsigned short*     sidx   = (unsigned short*)(smem_raw + SM_SIDX);
    unsigned short*     sstart = (unsigned short*)(smem_raw + SM_START);

    const int graph = blockIdx.x / CPG;
    const int base  = graph * NPER;
    const int tid   = threadIdx.x;

    for (int p = tid; p < NPER; p += TPB) {
        pts [p] = g_pts [graph][p];
        sidx[p] = g_sidx[graph][p];
    }
    for (int i = tid; i <= GC; i += TPB) sstart[i] = g_start[graph][i];
    __syncthreads();

    const int    s  = (blockIdx.x % CPG) * TPB + tid;   // sorted slot = query
    const float4 Q  = pts[s];
    const float  qx = Q.x, qy = Q.y, qz = Q.z, qs = Q.w;
    const int    qi = (int)sidx[s];                     // original local idx
    const int    qcx = cellCoord(qx), qcy = cellCoord(qy), qcz = cellCoord(qz);

    float bd[KP1];
    int   bi[KP1];
#pragma unroll
    for (int m = 0; m < KP1; ++m) { bd[m] = CUDART_INF_F; bi[m] = -1; }
    float worstf = CUDART_INF_F;
    bool  done = false;

    unsigned offb = 0;
    const unsigned pbase = (unsigned)__cvta_generic_to_shared(pend + tid);

    // ---- ring 1: the full 3x3x3 cube, row-merged -------------------------
    {
        const int x0 = max(qcx - 1, 0), x1 = min(qcx + 1, G - 1);
#pragma unroll 1
        for (int dz = -1; dz <= 1; ++dz) {
#pragma unroll 1
            for (int dy = -1; dy <= 1; ++dy) {
                const int  cy2 = qcy + dy, cz2 = qcz + dz;
                const bool rv  = ((unsigned)cy2 < G) && ((unsigned)cz2 < G);
                const int  rb  = (cz2 * G + cy2) * G;
                SCAN_SEG(rv, rb, x0, x1);
            }
        }
        DRAIN();
        const float bnd = HCELL;   // after ring r: unexamined points >= r*h
        if (bd[KP1 - 1] <= 0.998f * bnd * bnd) { done = true; worstf = -CUDART_INF_F; }
    }

    // ---- rings r >= 2: shells --------------------------------------------
#pragma unroll 1
    for (int r = 2; r <= G && __any_sync(0xFFFFFFFFu, !done); ++r) {
#pragma unroll 1
        for (int dz = -r; dz <= r; ++dz) {
#pragma unroll 1
            for (int dy = -r; dy <= r; ++dy) {
                const int  cy2 = qcy + dy, cz2 = qcz + dz;
                const bool rv  = ((unsigned)cy2 < G) && ((unsigned)cz2 < G);
                const int  rb  = (cz2 * G + cy2) * G;
                const bool edge = (dz == -r) | (dz == r) | (dy == -r) | (dy == r); // uniform
                if (edge) {
                    const int x0 = max(qcx - r, 0), x1 = min(qcx + r, G - 1);
                    SCAN_SEG(rv, rb, x0, x1);
                } else {
                    const int xl = qcx - r;
                    SCAN_SEG(rv && (xl >= 0), rb, xl, xl);
                    const int xr = qcx + r;
                    SCAN_SEG(rv && (xr < G), rb, xr, xr);
                }
            }
        }
        DRAIN();
        if (!done) {
            const float bnd = (float)r * HCELL;
            if (bd[KP1 - 1] <= 0.998f * bnd * bnd) { done = true; worstf = -CUDART_INF_F; }
        }
    }

    // Emit: drop the single self entry (idx == qi, d == +0), keep first K.
    const int    gq = base + qi;
    const size_t Nk = (size_t)total_n * K;
    int w = 0;
#pragma unroll
    for (int m = 0; m < KP1; ++m) {
        if (bi[m] != qi && w < K) {
            const size_t e = (size_t)gq * K + w;
            out[e]          = (float)(bi[m] + base);
            out[Nk + e]     = (float)gq;
            out[2 * Nk + e] = bd[m];
            ++w;
        }
    }
}

extern "C" void kernel_launch(void* const* d_in, const int* in_sizes, int n_in,
                              void* d_out, int out_size)
{
    const float* pos = (const float*)d_in[0];
    const int total_n = in_sizes[0] / 3;
    const int ngraphs = total_n / NPER;

    knn_build_kernel<<<ngraphs, TPB>>>(pos);

    cudaFuncSetAttribute(knn_query_kernel,
                         cudaFuncAttributeMaxDynamicSharedMemorySize, SM_TOTAL);
    knn_query_kernel<<<ngraphs * CPG, TPB, SM_TOTAL>>>((float*)d_out, total_n);
}

// round 9
// speedup vs baseline: 5.9825x; 5.9825x over previous
#include <cuda_runtime.h>
#include <math_constants.h>

// Exact kNN graph: uniform grid + per-lane ring cursors (warp-phase rings).
// PyG knn_graph(loop=False): B=16 graphs x n=4096 pts, D=3, k=16.
// Output (float32 flat): [nbr_global | centers | topk_d2], each total_n*K.

#define K     16
#define KP1   17
#define NPER  4096
#define TPB   256
#define CPG   (NPER / TPB)
#define NG    16
#define G     18
#define GC    (G * G * G)        // 5832
#define GCP   5888               // 256 * 23 (padded for the block scan)
#define LO    (-4.5f)
#define HCELL 0.5f

#define PB      6
#define SLOT_B  (TPB * 8u)       // 2048 B between a thread's FIFO slots
#define FLUSH_B (5u * SLOT_B)

// smem byte offsets (query kernel)
#define SM_PTS   0                          // float4[4096]   65536
#define SM_PEND  65536                      // u64[PB][256]   12288
#define SM_SIDX  (65536 + 12288)            // u16[4096]       8192
#define SM_START (65536 + 12288 + 8192)     // u16[GC+1]      11666
#define SM_TOTAL (65536 + 12288 + 8192 + 11680)

// INIT key: monotone(+inf)=0xFF800000 in hi, idx=~0 in lo. > any real key.
#define INIT_KEY 0xFF800000FFFFFFFFull

__device__ float4         g_pts  [NG][NPER];    // (x, y, z, |p|^2) cell-sorted
__device__ unsigned short g_sidx [NG][NPER];    // sorted slot -> original idx
__device__ unsigned short g_start[NG][GC + 1];  // cumulative cell starts

__device__ __forceinline__ int cellCoord(float v) {
    int c = (int)floorf((v - LO) * (1.0f / HCELL));
    return min(G - 1, max(0, c));
}

#define UNPACK2(lo, hi, in) \
    asm("mov.b64 {%0, %1}, %2;" : "=r"(lo), "=r"(hi) : "l"(in))

// ---------------------------------------------------------------- build ----
__global__ __launch_bounds__(TPB, 1)
void knn_build_kernel(const float* __restrict__ pos)
{
    __shared__ int cnt[GCP];
    __shared__ int partial[TPB];
    const int g = blockIdx.x, tid = threadIdx.x, base = g * NPER;
    const float* gp = pos + (size_t)base * 3;

    for (int i = tid; i < GCP; i += TPB) cnt[i] = 0;
    __syncthreads();

    for (int p = tid; p < NPER; p += TPB) {
        const float x = gp[3 * p], y = gp[3 * p + 1], z = gp[3 * p + 2];
        atomicAdd(&cnt[(cellCoord(z) * G + cellCoord(y)) * G + cellCoord(x)], 1);
    }
    __syncthreads();

    // exclusive scan over GCP (23 cells/thread)
    const int c0 = tid * 23;
    int s = 0;
    for (int i = 0; i < 23; ++i) s += cnt[c0 + i];
    partial[tid] = s;
    __syncthreads();
    if (tid == 0) {
        int run = 0;
        for (int t = 0; t < TPB; ++t) { const int v = partial[t]; partial[t] = run; run += v; }
    }
    __syncthreads();
    int run = partial[tid];
    for (int i = 0; i < 23; ++i) { const int v = cnt[c0 + i]; cnt[c0 + i] = run; run += v; }
    __syncthreads();

    for (int i = tid; i <= GC; i += TPB)
        g_start[g][i] = (unsigned short)cnt[i];
    __syncthreads();

    // scatter: norm op order matches the query dot chain -> self-dist == +0
    for (int p = tid; p < NPER; p += TPB) {
        const float x = gp[3 * p], y = gp[3 * p + 1], z = gp[3 * p + 2];
        const int id = (cellCoord(z) * G + cellCoord(y)) * G + cellCoord(x);
        const int slot = atomicAdd(&cnt[id], 1);
        g_pts [g][slot] = make_float4(x, y, z, fmaf(z, z, fmaf(y, y, x * x)));
        g_sidx[g][slot] = (unsigned short)p;
    }
}

// ---------------------------------------------------------------- query ----

// Drain this lane's FIFO into the sorted K+1 u64-key list. Exact key =
// (monotone dist bits << 32) | ORIGINAL idx: reproduces jax.lax.top_k's
// (value, lower-index) order exactly, independent of arrival order.
#define DRAIN()                                                               \
    {                                                                         \
        const int cnt_ = (int)(offb >> 11);                                   \
        offb = 0;                                                             \
        const unsigned long long* myp_ = pend + tid;                          \
        _Pragma("unroll 1")                                                   \
        for (int p_ = 0; p_ < cnt_; ++p_) {                                   \
            const unsigned long long kk_ = myp_[(size_t)p_ * TPB];            \
            unsigned lo_, hi_;                                                \
            UNPACK2(lo_, hi_, kk_);                                           \
            hi_ ^= ((unsigned)(((int)hi_) >> 31)) | 0x80000000u;              \
            unsigned long long key_ =                                         \
                ((unsigned long long)hi_ << 32) | (unsigned)sidx[lo_];        \
            if (key_ < bk[KP1 - 1]) {                                         \
                _Pragma("unroll")                                             \
                for (int m_ = 0; m_ < KP1; ++m_) {                            \
                    const bool sw_ = key_ < bk[m_];                           \
                    const unsigned long long l2_ = sw_ ? key_ : bk[m_];       \
                    key_   = sw_ ? bk[m_] : key_;                             \
                    bk[m_] = l2_;                                             \
                }                                                             \
            }                                                                 \
        }                                                                     \
        const unsigned wh_ = (unsigned)(bk[KP1 - 1] >> 32);                   \
        const unsigned wu_ = (wh_ & 0x80000000u) ? (wh_ ^ 0x80000000u) : ~wh_;\
        worstf = __uint_as_float(wu_);                                        \
    }

__global__ __launch_bounds__(TPB, 2)
void knn_query_kernel(float* __restrict__ out, int total_n)
{
    extern __shared__ char smraw[];
    float4*             pts    = (float4*)(smraw + SM_PTS);
    unsigned long long* pend   = (unsigned long long*)(smraw + SM_PEND);
    unsigned short*     sidx   = (unsigned short*)(smraw + SM_SIDX);
    unsigned short*     sstart = (unsigned short*)(smraw + SM_START);

    const int graph = blockIdx.x / CPG;
    const int base  = graph * NPER;
    const int tid   = threadIdx.x;

    for (int p = tid; p < NPER; p += TPB) {
        pts [p] = g_pts [graph][p];
        sidx[p] = g_sidx[graph][p];
    }
    for (int i = tid; i <= GC; i += TPB) sstart[i] = g_start[graph][i];
    __syncthreads();

    const int    s  = (blockIdx.x % CPG) * TPB + tid;   // sorted slot = query
    const float4 Q  = pts[s];
    const float  qx = Q.x, qy = Q.y, qz = Q.z, qs = Q.w;
    const int    qi = (int)sidx[s];
    const int    qcx = cellCoord(qx), qcy = cellCoord(qy), qcz = cellCoord(qz);

    unsigned long long bk[KP1];
#pragma unroll
    for (int m = 0; m < KP1; ++m) bk[m] = INIT_KEY;
    float worstf = CUDART_INF_F;

    unsigned offb = 0;
    const unsigned pbase = (unsigned)__cvta_generic_to_shared(pend + tid);

    bool done = false;

#pragma unroll 1
    for (int r = 1; r <= G; ++r) {
        // per-lane ring-r cursor (r==1: full 3x3x3 cube rows; r>=2: shell)
        int dz = -r, dy = -r, side = 0;
        unsigned cur = 0, end = 0;
        bool exhausted = done;

        while (true) {
            const bool needref = !exhausted && (cur == end);
            if (!__any_sync(0xFFFFFFFFu, (cur < end) | needref)) break;

            if (needref) {  // one refill step (short, divergent but rare-ish)
                const int  cz = qcz + dz, cy = qcy + dy;
                const bool rowv = ((unsigned)cz < G) & ((unsigned)cy < G);
                const int  rb = (cz * G + cy) * G;
                const bool fullrow =
                    (r == 1) | (dz == -r) | (dz == r) | (dy == -r) | (dy == r);
                bool adv;
                if (fullrow) {
                    if (rowv) {
                        const int x0 = max(qcx - r, 0);
                        const int x1 = min(qcx + r, G - 1);
                        cur = sstart[rb + x0];
                        end = sstart[rb + x1 + 1];
                    }
                    adv = true;
                } else if (side == 0) {   // interior shell row: left cell
                    const int x = qcx - r;
                    if (rowv & (x >= 0)) { cur = sstart[rb + x]; end = sstart[rb + x + 1]; }
                    side = 1; adv = false;
                } else {                  // interior shell row: right cell
                    const int x = qcx + r;
                    if (rowv & (x < G)) { cur = sstart[rb + x]; end = sstart[rb + x + 1]; }
                    side = 0; adv = true;
                }
                if (adv) { if (++dy > r) { dy = -r; if (++dz > r) exhausted = true; } }
            }

            if (cur < end) {   // one candidate from this lane's own segment
                const float4 P   = pts[cur];
                const float dot_ = fmaf(qz, P.z, fmaf(qy, P.y, qx * P.x));
                const float d_   = fmaf(-2.f, dot_, qs + P.w);  // reference op order
                unsigned long long kk_;
                asm("mov.b64 %0, {%1, %2};" : "=l"(kk_)
                    : "r"(cur), "r"(__float_as_uint(d_)));
                unsigned inc_;
                asm volatile(
                    "{\n\t.reg .pred p;\n\t"
                    "setp.le.f32 p, %1, %2;\n\t"
                    "selp.u32 %0, %3, 0, p;\n\t"
                    "@p st.shared.b64 [%4], %5;\n\t}"
                    : "=r"(inc_)
                    : "f"(d_), "f"(worstf), "n"(SLOT_B),
                      "r"(pbase + offb), "l"(kk_)
                    : "memory");
                offb += inc_;
                ++cur;
            }

            if (__any_sync(0xFFFFFFFFu, offb >= FLUSH_B)) DRAIN();
        }

        DRAIN();   // settle worstf before the stop test

        if (!done) {
            // After ring r every unexamined point is >= r*h away (holds under
            // clamping; 0.998 absorbs FP rounding, conservative direction).
            const float bnd = (float)r * HCELL;
            if (worstf <= 0.998f * bnd * bnd) done = true;
        }
        if (!__any_sync(0xFFFFFFFFu, !done)) break;
    }

    // Emit: drop the single self entry (idx == qi, d == +0), keep first K.
    const int    gq = base + qi;
    const size_t Nk = (size_t)total_n * K;
    int w = 0;
#pragma unroll
    for (int m = 0; m < KP1; ++m) {
        const int      idx = (int)(unsigned)bk[m];
        const unsigned hi  = (unsigned)(bk[m] >> 32);
        const unsigned du  = (hi & 0x80000000u) ? (hi ^ 0x80000000u) : ~hi;
        if (idx != qi && w < K) {
            const size_t e = (size_t)gq * K + w;
            out[e]          = (float)(idx + base);
            out[Nk + e]     = (float)gq;
            out[2 * Nk + e] = __uint_as_float(du);
            ++w;
        }
    }
}

extern "C" void kernel_launch(void* const* d_in, const int* in_sizes, int n_in,
                              void* d_out, int out_size)
{
    const float* pos = (const float*)d_in[0];
    const int total_n = in_sizes[0] / 3;
    const int ngraphs = total_n / NPER;

    knn_build_kernel<<<ngraphs, TPB>>>(pos);

    cudaFuncSetAttribute(knn_query_kernel,
                         cudaFuncAttributeMaxDynamicSharedMemorySize, SM_TOTAL);
    knn_query_kernel<<<ngraphs * CPG, TPB, SM_TOTAL>>>((float*)d_out, total_n);
}